// round 5
// baseline (speedup 1.0000x reference)
#include <cuda_runtime.h>
#include <cstdint>
#include <math.h>

#define EPSF 1e-6f
#define WARPS 8
#define NT    4      // tiles (of 32 edges) per warp, software-pipelined

// Padded node table: up to 131072 nodes * 2 float4 = 4 MB static scratch.
__device__ float4 g_npad[131072 * 2];

__global__ void pad_nodes_kernel(const float* __restrict__ nodes, int n_nodes) {
    int i = blockIdx.x * blockDim.x + threadIdx.x;
    if (i < n_nodes) {
        const float* p = nodes + (size_t)i * 7;
        g_npad[i * 2 + 0] = make_float4(p[0], p[1], p[2], p[3]);
        g_npad[i * 2 + 1] = make_float4(p[4], p[5], p[6], 0.0f);
    }
}

__device__ __forceinline__ uint32_t smem_u32(const void* p) {
    return (uint32_t)__cvta_generic_to_shared(p);
}
__device__ __forceinline__ void cp16(uint32_t dst, const void* src) {
    asm volatile("cp.async.cg.shared.global [%0], [%1], 16;" :: "r"(dst), "l"(src));
}
__device__ __forceinline__ void cp_commit() {
    asm volatile("cp.async.commit_group;" ::: "memory");
}
__device__ __forceinline__ void cp_wait1() {
    asm volatile("cp.async.wait_group 1;" ::: "memory");
}
__device__ __forceinline__ void cp_wait0() {
    asm volatile("cp.async.wait_group 0;" ::: "memory");
}

__device__ __forceinline__ float3 f3cross(float3 a, float3 b) {
    return make_float3(a.y * b.z - a.z * b.y,
                       a.z * b.x - a.x * b.z,
                       a.x * b.y - a.y * b.x);
}

__device__ __forceinline__ float3 qrot(float4 q, float3 v) {
    float3 u = make_float3(q.x, q.y, q.z);
    float3 t = f3cross(u, v);
    t.x *= 2.0f; t.y *= 2.0f; t.z *= 2.0f;
    float3 c = f3cross(u, t);
    return make_float3(v.x + q.w * t.x + c.x,
                       v.y + q.w * t.y + c.y,
                       v.z + q.w * t.z + c.z);
}

__device__ __forceinline__ float4 qmul(float4 a, float4 b) {
    return make_float4(
        a.w * b.x + a.x * b.w + a.y * b.z - a.z * b.y,
        a.w * b.y - a.x * b.z + a.y * b.w + a.z * b.x,
        a.w * b.z + a.x * b.y - a.y * b.x + a.z * b.w,
        a.w * b.w - a.x * b.x - a.y * b.y - a.z * b.z);
}

// Full per-edge SE(3) relative-pose error + log map.
__device__ __forceinline__ void edge_error(
    float p0, float p1, float p2, float p3, float p4, float p5, float p6,
    float4 n1a, float4 n1b, float4 n2a, float4 n2b,
    float& r0, float& r1, float& r2, float& r3, float& r4, float& r5)
{
    float3 t1 = make_float3(n1a.x, n1a.y, n1a.z);
    float4 q1 = make_float4(n1a.w, n1b.x, n1b.y, n1b.z);
    float3 t2 = make_float3(n2a.x, n2a.y, n2a.z);
    float4 q2 = make_float4(n2a.w, n2b.x, n2b.y, n2b.z);

    // A = inv(pose)
    float4 qa = make_float4(-p3, -p4, -p5, p6);
    float3 tp = make_float3(p0, p1, p2);
    float3 ra = qrot(qa, tp);
    float3 ta = make_float3(-ra.x, -ra.y, -ra.z);

    // B = A * node2
    float3 rb = qrot(qa, t2);
    float3 tb = make_float3(ta.x + rb.x, ta.y + rb.y, ta.z + rb.z);
    float4 qb = qmul(qa, q2);

    // C = inv(node1)
    float4 qc = make_float4(-q1.x, -q1.y, -q1.z, q1.w);
    float3 rc = qrot(qc, t1);
    float3 tc = make_float3(-rc.x, -rc.y, -rc.z);

    // E = B * C
    float3 re = qrot(qb, tc);
    float3 te = make_float3(tb.x + re.x, tb.y + re.y, tb.z + re.z);
    float4 qe = qmul(qb, qc);

    // se3_log using |qe| == 1:
    //   theta = 2*atan2(nn, w);  (1+cos th)/(2 th sin th) == w/(2 nn th)  exactly
    float nn2 = qe.x * qe.x + qe.y * qe.y + qe.z * qe.z;
    float nn  = sqrtf(nn2);
    float theta, scale;
    if (nn > EPSF) {
        theta = 2.0f * atan2f(nn, qe.w);
        scale = __fdividef(theta, nn);
    } else {
        float dw = (fabsf(qe.w) > EPSF) ? qe.w : 1.0f;
        scale = __fdividef(2.0f, dw);
        theta = fabsf(scale) * nn;   // tiny
    }
    float c;
    if (theta < EPSF) {
        c = 1.0f / 12.0f;
    } else {
        c = __fdividef(1.0f, theta * theta)
          - qe.w * __fdividef(0.5f, nn * theta);
    }

    float3 phi = make_float3(qe.x * scale, qe.y * scale, qe.z * scale);
    float3 pxt  = f3cross(phi, te);
    float3 ppxt = f3cross(phi, pxt);
    r0 = te.x - 0.5f * pxt.x + c * ppxt.x;
    r1 = te.y - 0.5f * pxt.y + c * ppxt.y;
    r2 = te.z - 0.5f * pxt.z + c * ppxt.z;
    r3 = phi.x; r4 = phi.y; r5 = phi.z;
}

__global__ __launch_bounds__(256)
void pose_graph_kernel(const int* __restrict__ edges,
                       const float* __restrict__ poses,
                       float* __restrict__ out,
                       int n_edges, int n_nodes)
{
    // Double-buffered per-warp staging (2 pipeline stages)
    __shared__ float4 s0[2][WARPS][64];   // first 16B of gathered nodes
    __shared__ float4 s1[2][WARPS][64];   // second 16B
    __shared__ float  sp[2][WARPS][224];  // poses: 32 edges * 7 floats
    __shared__ float  so[WARPS][192];     // output SoA: 6 comps * 32 edges

    const int warp = threadIdx.x >> 5;
    const int lane = threadIdx.x & 31;
    const long base = ((long)blockIdx.x * WARPS + warp) * (NT * 32);

    const int h  = lane & 1;       // which 16B half this lane fetches
    const int nl = lane >> 1;      // node-slot sub-index 0..15

    if (base + NT * 32 <= (long)n_edges) {
        // ================= fast, pipelined, warp-autonomous path =============
        const int2* E = (const int2*)edges;

        // -- prologue: issue tile 0, prefetch edges of tile 1 --
        int2 vg;  // edge indices for the NEXT tile to be issued
        {
            int2 v0 = __ldg(E + base + lane);
            int i1 = min(max(v0.x, 0), n_nodes - 1);
            int i2 = min(max(v0.y, 0), n_nodes - 1);
            uint32_t spA = smem_u32(&sp[0][warp][0]);
            const float4* P4 = (const float4*)(poses + (size_t)base * 7);
            cp16(spA + lane * 16, P4 + lane);
            if (lane < 24) cp16(spA + (32 + lane) * 16, P4 + 32 + lane);
            uint32_t s0A = smem_u32(&s0[0][warp][0]);
            uint32_t s1A = smem_u32(&s1[0][warp][0]);
            uint32_t dstBase = (h ? s1A : s0A);
#pragma unroll
            for (int j = 0; j < 4; j++) {
                int srcLane = ((j & 1) << 4) | nl;
                int idx = __shfl_sync(0xffffffffu, (j < 2) ? i1 : i2, srcLane);
                cp16(dstBase + (j * 16 + nl) * 16, &g_npad[idx * 2 + h]);
            }
            cp_commit();
            vg = __ldg(E + base + 32 + lane);   // edges of tile 1
        }

#pragma unroll
        for (int t = 0; t < NT; t++) {
            const int buf = t & 1;

            // -- issue stage for tile t+1 (into other buffer) --
            if (t + 1 < NT) {
                const long e0n = base + (t + 1) * 32;
                int i1 = min(max(vg.x, 0), n_nodes - 1);
                int i2 = min(max(vg.y, 0), n_nodes - 1);
                uint32_t spA = smem_u32(&sp[buf ^ 1][warp][0]);
                const float4* P4 = (const float4*)(poses + (size_t)e0n * 7);
                cp16(spA + lane * 16, P4 + lane);
                if (lane < 24) cp16(spA + (32 + lane) * 16, P4 + 32 + lane);
                uint32_t s0A = smem_u32(&s0[buf ^ 1][warp][0]);
                uint32_t s1A = smem_u32(&s1[buf ^ 1][warp][0]);
                uint32_t dstBase = (h ? s1A : s0A);
#pragma unroll
                for (int j = 0; j < 4; j++) {
                    int srcLane = ((j & 1) << 4) | nl;
                    int idx = __shfl_sync(0xffffffffu, (j < 2) ? i1 : i2, srcLane);
                    cp16(dstBase + (j * 16 + nl) * 16, &g_npad[idx * 2 + h]);
                }
                cp_commit();
                if (t + 2 < NT) vg = __ldg(E + base + (t + 2) * 32 + lane);
            }

            // -- wait for tile t's data (leave tile t+1's group in flight) --
            if (t + 1 < NT) cp_wait1(); else cp_wait0();
            __syncwarp();

            // -- compute tile t --
            float p0 = sp[buf][warp][lane * 7 + 0], p1 = sp[buf][warp][lane * 7 + 1];
            float p2 = sp[buf][warp][lane * 7 + 2], p3 = sp[buf][warp][lane * 7 + 3];
            float p4 = sp[buf][warp][lane * 7 + 4], p5 = sp[buf][warp][lane * 7 + 5];
            float p6 = sp[buf][warp][lane * 7 + 6];
            float4 n1a = s0[buf][warp][lane],      n1b = s1[buf][warp][lane];
            float4 n2a = s0[buf][warp][32 + lane], n2b = s1[buf][warp][32 + lane];

            float r0, r1, r2, r3, r4, r5;
            edge_error(p0, p1, p2, p3, p4, p5, p6, n1a, n1b, n2a, n2b,
                       r0, r1, r2, r3, r4, r5);

            // SoA staging (conflict-free STS)
            so[warp][0 * 32 + lane] = r0;
            so[warp][1 * 32 + lane] = r1;
            so[warp][2 * 32 + lane] = r2;
            so[warp][3 * 32 + lane] = r3;
            so[warp][4 * 32 + lane] = r4;
            so[warp][5 * 32 + lane] = r5;
            __syncwarp();

            // vectorized writeback: 48 float4
            float4* O4 = (float4*)(out + (size_t)(base + t * 32) * 6);
#pragma unroll
            for (int rep = 0; rep < 2; rep++) {
                int v = rep * 32 + lane;
                if (rep == 0 || lane < 16) {
                    int f = 4 * v;
                    float a0 = so[warp][((f    ) % 6) * 32 + ((f    ) / 6)];
                    float a1 = so[warp][((f + 1) % 6) * 32 + ((f + 1) / 6)];
                    float a2 = so[warp][((f + 2) % 6) * 32 + ((f + 2) / 6)];
                    float a3 = so[warp][((f + 3) % 6) * 32 + ((f + 3) / 6)];
                    O4[v] = make_float4(a0, a1, a2, a3);
                }
            }
            __syncwarp();  // so[] reused next iteration
        }
    } else {
        // ================= scalar tail path =================
        for (int k = 0; k < NT; k++) {
            long e = base + k * 32 + lane;
            if (e < (long)n_edges) {
                int2 vi = __ldg((const int2*)edges + e);
                int i1 = min(max(vi.x, 0), n_nodes - 1);
                int i2 = min(max(vi.y, 0), n_nodes - 1);
                const float* P = poses + (size_t)e * 7;
                float4 n1a = __ldg(&g_npad[i1 * 2 + 0]), n1b = __ldg(&g_npad[i1 * 2 + 1]);
                float4 n2a = __ldg(&g_npad[i2 * 2 + 0]), n2b = __ldg(&g_npad[i2 * 2 + 1]);
                float r0, r1, r2, r3, r4, r5;
                edge_error(P[0], P[1], P[2], P[3], P[4], P[5], P[6],
                           n1a, n1b, n2a, n2b, r0, r1, r2, r3, r4, r5);
                float* O = out + (size_t)e * 6;
                O[0] = r0; O[1] = r1; O[2] = r2; O[3] = r3; O[4] = r4; O[5] = r5;
            }
        }
    }
}

extern "C" void kernel_launch(void* const* d_in, const int* in_sizes, int n_in,
                              void* d_out, int out_size)
{
    // Identify inputs by size: nodes smallest, poses largest, edges remaining.
    int ie = 0, ip = 1, in_ = 2;
    {
        long s0 = in_sizes[0], s1 = in_sizes[1], s2 = in_sizes[2];
        in_ = (s0 <= s1 && s0 <= s2) ? 0 : (s1 <= s0 && s1 <= s2) ? 1 : 2;
        ip  = (s0 >= s1 && s0 >= s2) ? 0 : (s1 >= s0 && s1 >= s2) ? 1 : 2;
        ie  = 3 - in_ - ip;
    }

    const int*   edges = (const int*)d_in[ie];
    const float* poses = (const float*)d_in[ip];
    const float* nodes = (const float*)d_in[in_];
    float*       out   = (float*)d_out;

    int n_edges = in_sizes[ie] / 2;
    int n_nodes = in_sizes[in_] / 7;
    if (n_nodes > 131072) n_nodes = 131072;  // static scratch bound

    pad_nodes_kernel<<<(n_nodes + 255) / 256, 256>>>(nodes, n_nodes);
    int edges_per_block = WARPS * NT * 32;   // 1024
    int blocks = (n_edges + edges_per_block - 1) / edges_per_block;
    pose_graph_kernel<<<blocks, 256>>>(edges, poses, out, n_edges, n_nodes);
}

// round 6
// speedup vs baseline: 1.5426x; 1.5426x over previous
#include <cuda_runtime.h>
#include <cstdint>
#include <math.h>

#define EPSF 1e-6f
#define WARPS 8

// Padded node table: up to 131072 nodes * 2 float4 = 4 MB static scratch.
__device__ float4 g_npad[131072 * 2];

__global__ void pad_nodes_kernel(const float* __restrict__ nodes, int n_nodes) {
    int i = blockIdx.x * blockDim.x + threadIdx.x;
    if (i < n_nodes) {
        const float* p = nodes + (size_t)i * 7;
        g_npad[i * 2 + 0] = make_float4(p[0], p[1], p[2], p[3]);
        g_npad[i * 2 + 1] = make_float4(p[4], p[5], p[6], 0.0f);
    }
}

__device__ __forceinline__ uint32_t smem_u32(const void* p) {
    return (uint32_t)__cvta_generic_to_shared(p);
}
__device__ __forceinline__ void cp16(uint32_t dst, const void* src) {
    asm volatile("cp.async.cg.shared.global [%0], [%1], 16;" :: "r"(dst), "l"(src));
}
__device__ __forceinline__ void cp_commit_wait() {
    asm volatile("cp.async.commit_group;\n\tcp.async.wait_group 0;" ::: "memory");
}

__device__ __forceinline__ float3 f3cross(float3 a, float3 b) {
    return make_float3(a.y * b.z - a.z * b.y,
                       a.z * b.x - a.x * b.z,
                       a.x * b.y - a.y * b.x);
}

__device__ __forceinline__ float3 qrot(float4 q, float3 v) {
    float3 u = make_float3(q.x, q.y, q.z);
    float3 t = f3cross(u, v);
    t.x *= 2.0f; t.y *= 2.0f; t.z *= 2.0f;
    float3 c = f3cross(u, t);
    return make_float3(v.x + q.w * t.x + c.x,
                       v.y + q.w * t.y + c.y,
                       v.z + q.w * t.z + c.z);
}

__device__ __forceinline__ float4 qmul(float4 a, float4 b) {
    return make_float4(
        a.w * b.x + a.x * b.w + a.y * b.z - a.z * b.y,
        a.w * b.y - a.x * b.z + a.y * b.w + a.z * b.x,
        a.w * b.z + a.x * b.y - a.y * b.x + a.z * b.w,
        a.w * b.w - a.x * b.x - a.y * b.y - a.z * b.z);
}

// Full per-edge SE(3) relative-pose error + log map.
__device__ __forceinline__ void edge_error(
    float p0, float p1, float p2, float p3, float p4, float p5, float p6,
    float4 n1a, float4 n1b, float4 n2a, float4 n2b,
    float& r0, float& r1, float& r2, float& r3, float& r4, float& r5)
{
    float3 t1 = make_float3(n1a.x, n1a.y, n1a.z);
    float4 q1 = make_float4(n1a.w, n1b.x, n1b.y, n1b.z);
    float3 t2 = make_float3(n2a.x, n2a.y, n2a.z);
    float4 q2 = make_float4(n2a.w, n2b.x, n2b.y, n2b.z);

    // A = inv(pose)
    float4 qa = make_float4(-p3, -p4, -p5, p6);
    float3 tp = make_float3(p0, p1, p2);
    float3 ra = qrot(qa, tp);
    float3 ta = make_float3(-ra.x, -ra.y, -ra.z);

    // B = A * node2
    float3 rb = qrot(qa, t2);
    float3 tb = make_float3(ta.x + rb.x, ta.y + rb.y, ta.z + rb.z);
    float4 qb = qmul(qa, q2);

    // C = inv(node1)
    float4 qc = make_float4(-q1.x, -q1.y, -q1.z, q1.w);
    float3 rc = qrot(qc, t1);
    float3 tc = make_float3(-rc.x, -rc.y, -rc.z);

    // E = B * C
    float3 re = qrot(qb, tc);
    float3 te = make_float3(tb.x + re.x, tb.y + re.y, tb.z + re.z);
    float4 qe = qmul(qb, qc);

    // se3_log using |qe| == 1:
    //   theta = 2*atan2(nn, w);  (1+cos th)/(2 th sin th) == w/(2 nn th)  exactly
    float nn2 = qe.x * qe.x + qe.y * qe.y + qe.z * qe.z;
    float nn  = sqrtf(nn2);
    float theta, scale;
    if (nn > EPSF) {
        theta = 2.0f * atan2f(nn, qe.w);
        scale = __fdividef(theta, nn);
    } else {
        float dw = (fabsf(qe.w) > EPSF) ? qe.w : 1.0f;
        scale = __fdividef(2.0f, dw);
        theta = fabsf(scale) * nn;   // tiny
    }
    float c;
    if (theta < EPSF) {
        c = 1.0f / 12.0f;
    } else {
        c = __fdividef(1.0f, theta * theta)
          - qe.w * __fdividef(0.5f, nn * theta);
    }

    float3 phi = make_float3(qe.x * scale, qe.y * scale, qe.z * scale);
    float3 pxt  = f3cross(phi, te);
    float3 ppxt = f3cross(phi, pxt);
    r0 = te.x - 0.5f * pxt.x + c * ppxt.x;
    r1 = te.y - 0.5f * pxt.y + c * ppxt.y;
    r2 = te.z - 0.5f * pxt.z + c * ppxt.z;
    r3 = phi.x; r4 = phi.y; r5 = phi.z;
}

__global__ __launch_bounds__(256)
void pose_graph_kernel(const int* __restrict__ edges,
                       const float* __restrict__ poses,
                       float* __restrict__ out,
                       int n_edges, int n_nodes)
{
    __shared__ float4 s0[WARPS][64];    // first 16B of gathered node
    __shared__ float4 s1[WARPS][64];    // second 16B
    __shared__ float  sp[WARPS][224];   // poses in; REUSED as output SoA (192 floats)

    const int warp = threadIdx.x >> 5;
    const int lane = threadIdx.x & 31;
    const int ew0  = blockIdx.x * 256 + warp * 32;   // first edge of this warp
    const int e    = ew0 + lane;

    if (ew0 + 32 <= n_edges) {
        // ================= fast, warp-autonomous path =================
        int2 vi = __ldg((const int2*)edges + e);
        int i1 = min(max(vi.x, 0), n_nodes - 1);
        int i2 = min(max(vi.y, 0), n_nodes - 1);

        // stage poses: 56 float4 per warp, cp.async (L1-bypassing)
        const float4* P4 = (const float4*)(poses + (size_t)ew0 * 7);
        uint32_t spA = smem_u32(&sp[warp][0]);
        cp16(spA + lane * 16, P4 + lane);
        if (lane < 24) cp16(spA + (32 + lane) * 16, P4 + 32 + lane);

        // gather: 64 node-halves per warp; idx redistributed via shfl
        uint32_t s0A = smem_u32(&s0[warp][0]);
        uint32_t s1A = smem_u32(&s1[warp][0]);
        const int h  = lane & 1;       // which 16B half this lane fetches
        const int nl = lane >> 1;      // node-slot sub-index 0..15
        uint32_t dstBase = (h ? s1A : s0A);
#pragma unroll
        for (int j = 0; j < 4; j++) {
            int srcLane = ((j & 1) << 4) | nl;
            int idx = __shfl_sync(0xffffffffu, (j < 2) ? i1 : i2, srcLane);
            int n = j * 16 + nl;       // slots 0..31 = node1, 32..63 = node2
            cp16(dstBase + n * 16, &g_npad[idx * 2 + h]);
        }
        cp_commit_wait();
        __syncwarp();

        float p0 = sp[warp][lane * 7 + 0], p1 = sp[warp][lane * 7 + 1];
        float p2 = sp[warp][lane * 7 + 2], p3 = sp[warp][lane * 7 + 3];
        float p4 = sp[warp][lane * 7 + 4], p5 = sp[warp][lane * 7 + 5];
        float p6 = sp[warp][lane * 7 + 6];
        float4 n1a = s0[warp][lane],      n1b = s1[warp][lane];
        float4 n2a = s0[warp][32 + lane], n2b = s1[warp][32 + lane];

        float r0, r1, r2, r3, r4, r5;
        edge_error(p0, p1, p2, p3, p4, p5, p6, n1a, n1b, n2a, n2b,
                   r0, r1, r2, r3, r4, r5);

        // SoA staging into sp (pose values already consumed; same-warp
        // program order keeps the LDS above before these STS)
        __syncwarp();
        sp[warp][0 * 32 + lane] = r0;
        sp[warp][1 * 32 + lane] = r1;
        sp[warp][2 * 32 + lane] = r2;
        sp[warp][3 * 32 + lane] = r3;
        sp[warp][4 * 32 + lane] = r4;
        sp[warp][5 * 32 + lane] = r5;
        __syncwarp();

        // vectorized writeback: 48 float4 per warp
        float4* O4 = (float4*)(out + (size_t)ew0 * 6);
#pragma unroll
        for (int rep = 0; rep < 2; rep++) {
            int v = rep * 32 + lane;
            if (rep == 0 || lane < 16) {
                int f = 4 * v;
                float a0 = sp[warp][((f    ) % 6) * 32 + ((f    ) / 6)];
                float a1 = sp[warp][((f + 1) % 6) * 32 + ((f + 1) / 6)];
                float a2 = sp[warp][((f + 2) % 6) * 32 + ((f + 2) / 6)];
                float a3 = sp[warp][((f + 3) % 6) * 32 + ((f + 3) / 6)];
                O4[v] = make_float4(a0, a1, a2, a3);
            }
        }
    } else if (e < n_edges) {
        // ================= scalar tail path =================
        int2 vi = __ldg((const int2*)edges + e);
        int i1 = min(max(vi.x, 0), n_nodes - 1);
        int i2 = min(max(vi.y, 0), n_nodes - 1);
        const float* P = poses + (size_t)e * 7;
        float4 n1a = __ldg(&g_npad[i1 * 2 + 0]), n1b = __ldg(&g_npad[i1 * 2 + 1]);
        float4 n2a = __ldg(&g_npad[i2 * 2 + 0]), n2b = __ldg(&g_npad[i2 * 2 + 1]);
        float r0, r1, r2, r3, r4, r5;
        edge_error(P[0], P[1], P[2], P[3], P[4], P[5], P[6],
                   n1a, n1b, n2a, n2b, r0, r1, r2, r3, r4, r5);
        float* O = out + (size_t)e * 6;
        O[0] = r0; O[1] = r1; O[2] = r2; O[3] = r3; O[4] = r4; O[5] = r5;
    }
}

extern "C" void kernel_launch(void* const* d_in, const int* in_sizes, int n_in,
                              void* d_out, int out_size)
{
    // Identify inputs by size: nodes smallest, poses largest, edges remaining.
    int ie = 0, ip = 1, in_ = 2;
    {
        long s0 = in_sizes[0], s1 = in_sizes[1], s2 = in_sizes[2];
        in_ = (s0 <= s1 && s0 <= s2) ? 0 : (s1 <= s0 && s1 <= s2) ? 1 : 2;
        ip  = (s0 >= s1 && s0 >= s2) ? 0 : (s1 >= s0 && s1 >= s2) ? 1 : 2;
        ie  = 3 - in_ - ip;
    }

    const int*   edges = (const int*)d_in[ie];
    const float* poses = (const float*)d_in[ip];
    const float* nodes = (const float*)d_in[in_];
    float*       out   = (float*)d_out;

    int n_edges = in_sizes[ie] / 2;
    int n_nodes = in_sizes[in_] / 7;
    if (n_nodes > 131072) n_nodes = 131072;  // static scratch bound

    pad_nodes_kernel<<<(n_nodes + 255) / 256, 256>>>(nodes, n_nodes);
    int blocks = (n_edges + 255) / 256;
    pose_graph_kernel<<<blocks, 256>>>(edges, poses, out, n_edges, n_nodes);
}

// round 7
// speedup vs baseline: 1.5883x; 1.0297x over previous
#include <cuda_runtime.h>
#include <cstdint>
#include <math.h>

#define EPSF 1e-6f
#define WARPS 8

// Padded node table: up to 131072 nodes * 2 float4 = 4 MB static scratch.
__device__ float4 g_npad[131072 * 2];

__global__ void pad_nodes_kernel(const float* __restrict__ nodes, int n_nodes) {
    int i = blockIdx.x * blockDim.x + threadIdx.x;
    if (i < n_nodes) {
        const float* p = nodes + (size_t)i * 7;
        g_npad[i * 2 + 0] = make_float4(p[0], p[1], p[2], p[3]);
        g_npad[i * 2 + 1] = make_float4(p[4], p[5], p[6], 0.0f);
    }
}

__device__ __forceinline__ uint32_t smem_u32(const void* p) {
    return (uint32_t)__cvta_generic_to_shared(p);
}
__device__ __forceinline__ void cp16(uint32_t dst, const void* src) {
    asm volatile("cp.async.cg.shared.global [%0], [%1], 16;" :: "r"(dst), "l"(src));
}
__device__ __forceinline__ void cp_commit_wait() {
    asm volatile("cp.async.commit_group;\n\tcp.async.wait_group 0;" ::: "memory");
}

__device__ __forceinline__ float3 f3cross(float3 a, float3 b) {
    return make_float3(a.y * b.z - a.z * b.y,
                       a.z * b.x - a.x * b.z,
                       a.x * b.y - a.y * b.x);
}

__device__ __forceinline__ float3 qrot(float4 q, float3 v) {
    float3 u = make_float3(q.x, q.y, q.z);
    float3 t = f3cross(u, v);
    t.x *= 2.0f; t.y *= 2.0f; t.z *= 2.0f;
    float3 c = f3cross(u, t);
    return make_float3(v.x + q.w * t.x + c.x,
                       v.y + q.w * t.y + c.y,
                       v.z + q.w * t.z + c.z);
}

__device__ __forceinline__ float4 qmul(float4 a, float4 b) {
    return make_float4(
        a.w * b.x + a.x * b.w + a.y * b.z - a.z * b.y,
        a.w * b.y - a.x * b.z + a.y * b.w + a.z * b.x,
        a.w * b.z + a.x * b.y - a.y * b.x + a.z * b.w,
        a.w * b.w - a.x * b.x - a.y * b.y - a.z * b.z);
}

// Branchless atan2(y, x) for y >= 0. Max abs error ~1e-5 rad (budget 1e-3).
__device__ __forceinline__ float fast_atan2_pos(float y, float x) {
    float ax = fabsf(x);
    float mn = fminf(ax, y), mx = fmaxf(ax, y);
    float t  = __fdividef(mn, mx);
    float t2 = t * t;
    float p  = fmaf(t2, fmaf(t2, fmaf(t2, fmaf(t2,
                0.0208351f, -0.085133f), 0.180141f), -0.3302995f), 0.9998660f);
    float at = p * t;
    at = (y > ax)    ? (1.57079632679f - at) : at;
    at = (x < 0.0f)  ? (3.14159265359f - at) : at;
    return at;
}

// Full per-edge SE(3) relative-pose error + log map.
// Algebraic reductions (exact):
//   t_B = qrot(qa, t2 - tp)                    [rotation is linear]
//   t_E = t_B - qrot(q_E, t1)                  [qrot(qB, qrot(qc,t1)) = qrot(qB*qc, t1)]
__device__ __forceinline__ void edge_error(
    float p0, float p1, float p2, float p3, float p4, float p5, float p6,
    float4 n1a, float4 n1b, float4 n2a, float4 n2b,
    float& r0, float& r1, float& r2, float& r3, float& r4, float& r5)
{
    float3 t1 = make_float3(n1a.x, n1a.y, n1a.z);
    float4 q1 = make_float4(n1a.w, n1b.x, n1b.y, n1b.z);
    float3 t2 = make_float3(n2a.x, n2a.y, n2a.z);
    float4 q2 = make_float4(n2a.w, n2b.x, n2b.y, n2b.z);

    // qa = conj(pose.q)
    float4 qa = make_float4(-p3, -p4, -p5, p6);

    // t_B = qrot(qa, t2 - tp)
    float3 d  = make_float3(t2.x - p0, t2.y - p1, t2.z - p2);
    float3 tb = qrot(qa, d);

    // q_E = (qa * q2) * conj(q1)
    float4 qb = qmul(qa, q2);
    float4 qc = make_float4(-q1.x, -q1.y, -q1.z, q1.w);
    float4 qe = qmul(qb, qc);

    // t_E = t_B - qrot(q_E, t1)
    float3 re = qrot(qe, t1);
    float3 te = make_float3(tb.x - re.x, tb.y - re.y, tb.z - re.z);

    // se3_log using |qe| == 1:
    //   theta = 2*atan2(nn, w);  (1+cos th)/(2 th sin th) == w/(2 nn th)  exactly
    float nn2 = qe.x * qe.x + qe.y * qe.y + qe.z * qe.z;
    float nn  = sqrtf(nn2);
    float theta, scale;
    if (nn > EPSF) {
        theta = 2.0f * fast_atan2_pos(nn, qe.w);
        scale = __fdividef(theta, nn);
    } else {
        float dw = (fabsf(qe.w) > EPSF) ? qe.w : 1.0f;
        scale = __fdividef(2.0f, dw);
        theta = fabsf(scale) * nn;   // tiny
    }
    float c;
    if (theta < EPSF) {
        c = 1.0f / 12.0f;
    } else {
        c = __fdividef(1.0f, theta * theta)
          - qe.w * __fdividef(0.5f, nn * theta);
    }

    float3 phi = make_float3(qe.x * scale, qe.y * scale, qe.z * scale);
    float3 pxt  = f3cross(phi, te);
    float3 ppxt = f3cross(phi, pxt);
    r0 = te.x - 0.5f * pxt.x + c * ppxt.x;
    r1 = te.y - 0.5f * pxt.y + c * ppxt.y;
    r2 = te.z - 0.5f * pxt.z + c * ppxt.z;
    r3 = phi.x; r4 = phi.y; r5 = phi.z;
}

__global__ __launch_bounds__(256)
void pose_graph_kernel(const int* __restrict__ edges,
                       const float* __restrict__ poses,
                       float* __restrict__ out,
                       int n_edges, int n_nodes)
{
    __shared__ float4 s0[WARPS][64];    // first 16B of gathered node
    __shared__ float4 s1[WARPS][64];    // second 16B
    __shared__ float  sp[WARPS][224];   // poses in; REUSED as output SoA (192 floats)

    const int warp = threadIdx.x >> 5;
    const int lane = threadIdx.x & 31;
    const int ew0  = blockIdx.x * 256 + warp * 32;   // first edge of this warp
    const int e    = ew0 + lane;

    if (ew0 + 32 <= n_edges) {
        // ================= fast, warp-autonomous path =================
        int2 vi = __ldg((const int2*)edges + e);
        int i1 = min(max(vi.x, 0), n_nodes - 1);
        int i2 = min(max(vi.y, 0), n_nodes - 1);

        // stage poses: 56 float4 per warp, cp.async (L1-bypassing)
        const float4* P4 = (const float4*)(poses + (size_t)ew0 * 7);
        uint32_t spA = smem_u32(&sp[warp][0]);
        cp16(spA + lane * 16, P4 + lane);
        if (lane < 24) cp16(spA + (32 + lane) * 16, P4 + 32 + lane);

        // gather: 64 node-halves per warp; idx redistributed via shfl;
        // lane pairs fetch the two halves of the same node (same 128B line)
        uint32_t s0A = smem_u32(&s0[warp][0]);
        uint32_t s1A = smem_u32(&s1[warp][0]);
        const int h  = lane & 1;
        const int nl = lane >> 1;
        uint32_t dstBase = (h ? s1A : s0A);
#pragma unroll
        for (int j = 0; j < 4; j++) {
            int srcLane = ((j & 1) << 4) | nl;
            int idx = __shfl_sync(0xffffffffu, (j < 2) ? i1 : i2, srcLane);
            int n = j * 16 + nl;       // slots 0..31 = node1, 32..63 = node2
            cp16(dstBase + n * 16, &g_npad[idx * 2 + h]);
        }
        cp_commit_wait();
        __syncwarp();

        float p0 = sp[warp][lane * 7 + 0], p1 = sp[warp][lane * 7 + 1];
        float p2 = sp[warp][lane * 7 + 2], p3 = sp[warp][lane * 7 + 3];
        float p4 = sp[warp][lane * 7 + 4], p5 = sp[warp][lane * 7 + 5];
        float p6 = sp[warp][lane * 7 + 6];
        float4 n1a = s0[warp][lane],      n1b = s1[warp][lane];
        float4 n2a = s0[warp][32 + lane], n2b = s1[warp][32 + lane];

        float r0, r1, r2, r3, r4, r5;
        edge_error(p0, p1, p2, p3, p4, p5, p6, n1a, n1b, n2a, n2b,
                   r0, r1, r2, r3, r4, r5);

        // SoA staging into sp (pose values already consumed)
        __syncwarp();
        sp[warp][0 * 32 + lane] = r0;
        sp[warp][1 * 32 + lane] = r1;
        sp[warp][2 * 32 + lane] = r2;
        sp[warp][3 * 32 + lane] = r3;
        sp[warp][4 * 32 + lane] = r4;
        sp[warp][5 * 32 + lane] = r5;
        __syncwarp();

        // vectorized writeback: 48 float4 per warp
        float4* O4 = (float4*)(out + (size_t)ew0 * 6);
#pragma unroll
        for (int rep = 0; rep < 2; rep++) {
            int v = rep * 32 + lane;
            if (rep == 0 || lane < 16) {
                int f = 4 * v;
                float a0 = sp[warp][((f    ) % 6) * 32 + ((f    ) / 6)];
                float a1 = sp[warp][((f + 1) % 6) * 32 + ((f + 1) / 6)];
                float a2 = sp[warp][((f + 2) % 6) * 32 + ((f + 2) / 6)];
                float a3 = sp[warp][((f + 3) % 6) * 32 + ((f + 3) / 6)];
                O4[v] = make_float4(a0, a1, a2, a3);
            }
        }
    } else if (e < n_edges) {
        // ================= scalar tail path =================
        int2 vi = __ldg((const int2*)edges + e);
        int i1 = min(max(vi.x, 0), n_nodes - 1);
        int i2 = min(max(vi.y, 0), n_nodes - 1);
        const float* P = poses + (size_t)e * 7;
        float4 n1a = __ldg(&g_npad[i1 * 2 + 0]), n1b = __ldg(&g_npad[i1 * 2 + 1]);
        float4 n2a = __ldg(&g_npad[i2 * 2 + 0]), n2b = __ldg(&g_npad[i2 * 2 + 1]);
        float r0, r1, r2, r3, r4, r5;
        edge_error(P[0], P[1], P[2], P[3], P[4], P[5], P[6],
                   n1a, n1b, n2a, n2b, r0, r1, r2, r3, r4, r5);
        float* O = out + (size_t)e * 6;
        O[0] = r0; O[1] = r1; O[2] = r2; O[3] = r3; O[4] = r4; O[5] = r5;
    }
}

extern "C" void kernel_launch(void* const* d_in, const int* in_sizes, int n_in,
                              void* d_out, int out_size)
{
    // Identify inputs by size: nodes smallest, poses largest, edges remaining.
    int ie = 0, ip = 1, in_ = 2;
    {
        long s0 = in_sizes[0], s1 = in_sizes[1], s2 = in_sizes[2];
        in_ = (s0 <= s1 && s0 <= s2) ? 0 : (s1 <= s0 && s1 <= s2) ? 1 : 2;
        ip  = (s0 >= s1 && s0 >= s2) ? 0 : (s1 >= s0 && s1 >= s2) ? 1 : 2;
        ie  = 3 - in_ - ip;
    }

    const int*   edges = (const int*)d_in[ie];
    const float* poses = (const float*)d_in[ip];
    const float* nodes = (const float*)d_in[in_];
    float*       out   = (float*)d_out;

    int n_edges = in_sizes[ie] / 2;
    int n_nodes = in_sizes[in_] / 7;
    if (n_nodes > 131072) n_nodes = 131072;  // static scratch bound

    pad_nodes_kernel<<<(n_nodes + 255) / 256, 256>>>(nodes, n_nodes);
    int blocks = (n_edges + 255) / 256;
    pose_graph_kernel<<<blocks, 256>>>(edges, poses, out, n_edges, n_nodes);
}